// round 15
// baseline (speedup 1.0000x reference)
#include <cuda_runtime.h>
#include <cuda_bf16.h>
#include <math.h>

#define HID 768
#define NSPLITS 12
#define H 6
#define D 64
#define AH 384
#define KS 9
#define PAD 4
#define BB 4
#define S 1024
#define OUT_W 768
#define CKN 54      // H*KS

// ---------------- scratch (device globals; no allocation allowed) ----------------
__device__ float g_mq[(size_t)BB * S * AH];
__device__ float g_mk[(size_t)BB * S * AH];
__device__ float g_mv[(size_t)BB * S * AH];
__device__ float g_co[(size_t)BB * S * AH];
__device__ float g_convattn[(size_t)BB * S * AH];      // mkc, then *= mq in place
__device__ float g_dw[(size_t)BB * S * HID];
__device__ float g_tdsm[(size_t)BB * S];
__device__ float g_ck[(size_t)BB * S * 64];            // padded ck logits
__device__ float g_ckWp[(size_t)AH * 64];              // padded ck_W

// ---------------- common helpers ----------------
__device__ __forceinline__ unsigned f2tf32(float x) {
    unsigned y;
    asm("cvt.rna.tf32.f32 %0, %1;" : "=r"(y) : "f"(x));
    return y;
}

__device__ __forceinline__ void mma8(float* c, const unsigned* a, const unsigned* b) {
    asm volatile("mma.sync.aligned.m16n8k8.row.col.f32.tf32.tf32.f32 "
        "{%0,%1,%2,%3},{%4,%5,%6,%7},{%8,%9},{%0,%1,%2,%3};"
        : "+f"(c[0]), "+f"(c[1]), "+f"(c[2]), "+f"(c[3])
        : "r"(a[0]), "r"(a[1]), "r"(a[2]), "r"(a[3]), "r"(b[0]), "r"(b[1]));
}

__device__ __forceinline__ unsigned smem_u32(const void* p) {
    return (unsigned)__cvta_generic_to_shared(p);
}
#define CP16(dst, src) asm volatile("cp.async.ca.shared.global [%0], [%1], 16;" :: "r"(dst), "l"(src))
#define CPCOMMIT()     asm volatile("cp.async.commit_group;")
#define CPWAIT(n)      asm volatile("cp.async.wait_group %0;" :: "n"(n))

__device__ __forceinline__ float wmaxf(float v) {
#pragma unroll
    for (int o = 16; o; o >>= 1) v = fmaxf(v, __shfl_xor_sync(0xffffffffu, v, o));
    return v;
}
__device__ __forceinline__ float wsumf(float v) {
#pragma unroll
    for (int o = 16; o; o >>= 1) v += __shfl_xor_sync(0xffffffffu, v, o);
    return v;
}

// ================= pipelined TF32 GEMM, narrow core (BM128 x BN64) =================
#define PAS_LD 36
#define PBS_LDT 36   // BT: [n][k]
#define PBS_LDN 72   // !BT: [k][n]
#define PA_STG (128 * PAS_LD)
#define PB_STG (64 * PBS_LDT)
#define PIPE_SMEM ((2 * PA_STG + 2 * PB_STG) * 4)  // 55296 B

template<bool BT>
__device__ __forceinline__ void gemm_core_pipe(
    const float* __restrict__ A, const float* __restrict__ Bm,
    float* __restrict__ C, int K, int lda, int ldb, int ldc, float alpha)
{
    extern __shared__ float dyn[];
    float* sA = dyn;
    float* sB = dyn + 2 * PA_STG;

    const int tid  = threadIdx.x;
    const int warp = tid >> 5, lane = tid & 31;
    const int g    = lane >> 2, tig = lane & 3;
    const int wm   = (warp >> 1) * 32, wn = (warp & 1) * 32;
    const int m0   = blockIdx.y * 128;
    const int n0   = blockIdx.x * 64;

    float acc[2][4][4];
#pragma unroll
    for (int mt = 0; mt < 2; mt++)
#pragma unroll
        for (int nt = 0; nt < 4; nt++)
#pragma unroll
            for (int e = 0; e < 4; e++) acc[mt][nt][e] = 0.f;

    const int nk = K >> 5;

    auto loadStage = [&](int ki, int st) {
        const int kbase = ki * 32;
#pragma unroll
        for (int it = 0; it < 4; it++) {
            int lin = tid + it * 256;
            int m = lin >> 3, kq = lin & 7;
            CP16(smem_u32(&sA[st * PA_STG + m * PAS_LD + kq * 4]),
                 A + (long long)(m0 + m) * lda + kbase + kq * 4);
        }
        if (BT) {
#pragma unroll
            for (int it = 0; it < 2; it++) {
                int lin = tid + it * 256;
                int n = lin >> 3, kq = lin & 7;
                CP16(smem_u32(&sB[st * PB_STG + n * PBS_LDT + kq * 4]),
                     Bm + (long long)(n0 + n) * ldb + kbase + kq * 4);
            }
        } else {
#pragma unroll
            for (int it = 0; it < 2; it++) {
                int lin = tid + it * 256;
                int k = lin >> 4, nq = lin & 15;
                CP16(smem_u32(&sB[st * PB_STG + k * PBS_LDN + nq * 4]),
                     Bm + (long long)(kbase + k) * ldb + n0 + nq * 4);
            }
        }
        CPCOMMIT();
    };

    loadStage(0, 0);
    for (int i = 0; i < nk; i++) {
        if (i + 1 < nk) { loadStage(i + 1, (i + 1) & 1); CPWAIT(1); }
        else            { CPWAIT(0); }
        __syncthreads();

        const float* as = &sA[(i & 1) * PA_STG];
        const float* bs = &sB[(i & 1) * PB_STG];
#pragma unroll
        for (int kk = 0; kk < 4; kk++) {
            const int kb = kk * 8;
            unsigned aF[2][4], bF[4][2];
#pragma unroll
            for (int mt = 0; mt < 2; mt++) {
                int mr = wm + mt * 16 + g;
                aF[mt][0] = f2tf32(as[mr * PAS_LD + kb + tig]);
                aF[mt][1] = f2tf32(as[(mr + 8) * PAS_LD + kb + tig]);
                aF[mt][2] = f2tf32(as[mr * PAS_LD + kb + tig + 4]);
                aF[mt][3] = f2tf32(as[(mr + 8) * PAS_LD + kb + tig + 4]);
            }
#pragma unroll
            for (int nt = 0; nt < 4; nt++) {
                int nc = wn + nt * 8 + g;
                if (BT) {
                    bF[nt][0] = f2tf32(bs[nc * PBS_LDT + kb + tig]);
                    bF[nt][1] = f2tf32(bs[nc * PBS_LDT + kb + tig + 4]);
                } else {
                    bF[nt][0] = f2tf32(bs[(kb + tig) * PBS_LDN + nc]);
                    bF[nt][1] = f2tf32(bs[(kb + tig + 4) * PBS_LDN + nc]);
                }
            }
#pragma unroll
            for (int mt = 0; mt < 2; mt++)
#pragma unroll
                for (int nt = 0; nt < 4; nt++)
                    mma8(acc[mt][nt], aF[mt], bF[nt]);
        }
        __syncthreads();
    }

#pragma unroll
    for (int mt = 0; mt < 2; mt++) {
#pragma unroll
        for (int nt = 0; nt < 4; nt++) {
            int gm0 = m0 + wm + mt * 16 + g;
            int gn0 = n0 + wn + nt * 8 + tig * 2;
            float* c = acc[mt][nt];
#pragma unroll
            for (int e = 0; e < 4; e++) {
                int gm = gm0 + (e >> 1) * 8;
                int gn = gn0 + (e & 1);
                C[(long long)gm * ldc + gn] = c[e] * alpha;
            }
        }
    }
}

// ================= wide core (BM128 x BN128), 8 warps of 32x64 =================
#define WAS_LD 36
#define WBS_LDT 36
#define WBS_LDN 136
#define WA_STG (128 * WAS_LD)
#define WB_STG (128 * WBS_LDT)
#define WIDE_SMEM ((2 * WA_STG + 2 * WB_STG) * 4)  // 73728 B

template<bool BT>
__device__ __forceinline__ void gemm_core_wide(
    const float* __restrict__ A, const float* __restrict__ Bm,
    const float* __restrict__ bias, float* __restrict__ C,
    int K, int lda, int ldb, int ldc, float alpha)
{
    extern __shared__ float dyn[];
    float* sA = dyn;
    float* sB = dyn + 2 * WA_STG;

    const int tid  = threadIdx.x;
    const int warp = tid >> 5, lane = tid & 31;
    const int g    = lane >> 2, tig = lane & 3;
    const int wm   = (warp >> 1) * 32, wn = (warp & 1) * 64;
    const int m0   = blockIdx.y * 128;
    const int n0   = blockIdx.x * 128;

    float acc[2][8][4];
#pragma unroll
    for (int mt = 0; mt < 2; mt++)
#pragma unroll
        for (int nt = 0; nt < 8; nt++)
#pragma unroll
            for (int e = 0; e < 4; e++) acc[mt][nt][e] = 0.f;

    const int nk = K >> 5;

    auto loadStage = [&](int ki, int st) {
        const int kbase = ki * 32;
#pragma unroll
        for (int it = 0; it < 4; it++) {
            int lin = tid + it * 256;
            int m = lin >> 3, kq = lin & 7;
            CP16(smem_u32(&sA[st * WA_STG + m * WAS_LD + kq * 4]),
                 A + (long long)(m0 + m) * lda + kbase + kq * 4);
        }
        if (BT) {
#pragma unroll
            for (int it = 0; it < 4; it++) {
                int lin = tid + it * 256;
                int n = lin >> 3, kq = lin & 7;
                CP16(smem_u32(&sB[st * WB_STG + n * WBS_LDT + kq * 4]),
                     Bm + (long long)(n0 + n) * ldb + kbase + kq * 4);
            }
        } else {
#pragma unroll
            for (int it = 0; it < 4; it++) {
                int lin = tid + it * 256;
                int k = lin >> 5, nq = lin & 31;
                CP16(smem_u32(&sB[st * WB_STG + k * WBS_LDN + nq * 4]),
                     Bm + (long long)(kbase + k) * ldb + n0 + nq * 4);
            }
        }
        CPCOMMIT();
    };

    loadStage(0, 0);
    for (int i = 0; i < nk; i++) {
        if (i + 1 < nk) { loadStage(i + 1, (i + 1) & 1); CPWAIT(1); }
        else            { CPWAIT(0); }
        __syncthreads();

        const float* as = &sA[(i & 1) * WA_STG];
        const float* bs = &sB[(i & 1) * WB_STG];
#pragma unroll
        for (int kk = 0; kk < 4; kk++) {
            const int kb = kk * 8;
            unsigned aF[2][4], bF[8][2];
#pragma unroll
            for (int mt = 0; mt < 2; mt++) {
                int mr = wm + mt * 16 + g;
                aF[mt][0] = f2tf32(as[mr * WAS_LD + kb + tig]);
                aF[mt][1] = f2tf32(as[(mr + 8) * WAS_LD + kb + tig]);
                aF[mt][2] = f2tf32(as[mr * WAS_LD + kb + tig + 4]);
                aF[mt][3] = f2tf32(as[(mr + 8) * WAS_LD + kb + tig + 4]);
            }
#pragma unroll
            for (int nt = 0; nt < 8; nt++) {
                int nc = wn + nt * 8 + g;
                if (BT) {
                    bF[nt][0] = f2tf32(bs[nc * WBS_LDT + kb + tig]);
                    bF[nt][1] = f2tf32(bs[nc * WBS_LDT + kb + tig + 4]);
                } else {
                    bF[nt][0] = f2tf32(bs[(kb + tig) * WBS_LDN + nc]);
                    bF[nt][1] = f2tf32(bs[(kb + tig + 4) * WBS_LDN + nc]);
                }
            }
#pragma unroll
            for (int mt = 0; mt < 2; mt++)
#pragma unroll
                for (int nt = 0; nt < 8; nt++)
                    mma8(acc[mt][nt], aF[mt], bF[nt]);
        }
        __syncthreads();
    }

#pragma unroll
    for (int mt = 0; mt < 2; mt++) {
#pragma unroll
        for (int nt = 0; nt < 8; nt++) {
            int gm0 = m0 + wm + mt * 16 + g;
            int gn0 = n0 + wn + nt * 8 + tig * 2;
            float* c = acc[mt][nt];
#pragma unroll
            for (int e = 0; e < 4; e++) {
                int gm = gm0 + (e >> 1) * 8;
                int gn = gn0 + (e & 1);
                float v = c[e] * alpha;
                if (bias) v += bias[gn];
                C[(long long)gm * ldc + gn] = v;
            }
        }
    }
}

// ---- 5 projections (Q,K,V,co,pw) in a single wide launch ----
struct Proj5 {
    const float* A[5];
    const float* B[5];
    const float* bias[5];
    float* C[5];
    int bt[5];
    int ldb[5];
};

__global__ __launch_bounds__(256) void tf32_proj5_w(Proj5 p)
{
    int op = blockIdx.z;
    if (p.bt[op])
        gemm_core_wide<true>(p.A[op], p.B[op], p.bias[op], p.C[op],
                             HID, HID, p.ldb[op], AH, 1.f);
    else
        gemm_core_wide<false>(p.A[op], p.B[op], p.bias[op], p.C[op],
                              HID, HID, p.ldb[op], AH, 1.f);
}

// ---- ck GEMM (narrow core) ----
__global__ __launch_bounds__(256) void ck_gemm_kernel(
    const float* __restrict__ ca, const float* __restrict__ ckWp, float* __restrict__ ck)
{
    gemm_core_pipe<false>(ca, ckWp, ck, AH, AH, 64, 64, 1.f);
}

// ================= fused attention: QK^T + dist_func + double softmax + PV =========
// Block: 16 query rows of one (b,h). smem: score tile 16x1028 + Q + K/V stages + mask/td.
#define FR 16
#define FS_LD 1028
#define FKV_STG (128 * 72)   // 9216 floats per stage
#define FUSED_SMEM ((FR * FS_LD + FR * 68 + 2 * FKV_STG + S + S) * 4)

__global__ __launch_bounds__(256) void attn_fused_kernel(
    const int* __restrict__ mask, const float* __restrict__ gammas,
    float* __restrict__ out)
{
    extern __shared__ float dyn[];
    float* sS  = dyn;                        // [FR][FS_LD]
    float* sQ  = sS + FR * FS_LD;            // [FR][68]
    float* sKV = sQ + FR * 68;               // [2][128*72]
    float* sM  = sKV + 2 * FKV_STG;          // [S]  mask as float
    float* sT  = sM + S;                     // [S]  td softmax row

    const int tid  = threadIdx.x;
    const int warp = tid >> 5, lane = tid & 31;
    const int g    = lane >> 2, tig = lane & 3;
    const int i0   = blockIdx.x * FR;
    const int b    = blockIdx.y / H;
    const int h    = blockIdx.y % H;

    // ---- stage K chunk 0 (async), then Q + mask + td (sync loads) ----
    auto stageK = [&](int jc, int st) {
#pragma unroll
        for (int it = 0; it < 8; it++) {
            int lin = tid + it * 256;
            int n = lin >> 4, kq = lin & 15;
            CP16(smem_u32(&sKV[st * FKV_STG + n * 68 + kq * 4]),
                 &g_mk[((size_t)b * S + jc * 128 + n) * AH + h * 64 + kq * 4]);
        }
        CPCOMMIT();
    };
    auto stageV = [&](int jc, int st) {
#pragma unroll
        for (int it = 0; it < 8; it++) {
            int lin = tid + it * 256;
            int k = lin >> 4, nq = lin & 15;
            CP16(smem_u32(&sKV[st * FKV_STG + k * 72 + nq * 4]),
                 &g_mv[((size_t)b * S + jc * 128 + k) * AH + h * 64 + nq * 4]);
        }
        CPCOMMIT();
    };

    stageK(0, 0);
    {
        int m = tid >> 4, kq = tid & 15;    // 256 threads = 16 rows x 16 quads
        float4 v = *reinterpret_cast<const float4*>(
            &g_mq[((size_t)b * S + i0 + m) * AH + h * 64 + kq * 4]);
        *reinterpret_cast<float4*>(&sQ[m * 68 + kq * 4]) = v;
    }
    for (int j = tid; j < S; j += 256) {
        sM[j] = (mask[b * S + j] != 0) ? 1.f : 0.f;
        sT[j] = g_tdsm[b * S + j];
    }
    __syncthreads();

    // ---- Phase A: scores tile = 0.125 * Q16x64 @ K^T, 8 chunks of 128 cols ----
    for (int jc = 0; jc < 8; jc++) {
        if (jc < 7) { stageK(jc + 1, (jc + 1) & 1); CPWAIT(1); }
        else        { CPWAIT(0); }
        __syncthreads();
        const float* bs = &sKV[(jc & 1) * FKV_STG];

        float acc[2][4];
#pragma unroll
        for (int nt = 0; nt < 2; nt++)
#pragma unroll
            for (int e = 0; e < 4; e++) acc[nt][e] = 0.f;

#pragma unroll
        for (int kk = 0; kk < 8; kk++) {
            int kb = kk * 8;
            unsigned aF[4];
            aF[0] = f2tf32(sQ[g * 68 + kb + tig]);
            aF[1] = f2tf32(sQ[(g + 8) * 68 + kb + tig]);
            aF[2] = f2tf32(sQ[g * 68 + kb + tig + 4]);
            aF[3] = f2tf32(sQ[(g + 8) * 68 + kb + tig + 4]);
#pragma unroll
            for (int nt = 0; nt < 2; nt++) {
                int nc = warp * 16 + nt * 8 + g;
                unsigned bF[2];
                bF[0] = f2tf32(bs[nc * 68 + kb + tig]);
                bF[1] = f2tf32(bs[nc * 68 + kb + tig + 4]);
                mma8(acc[nt], aF, bF);
            }
        }
#pragma unroll
        for (int nt = 0; nt < 2; nt++)
#pragma unroll
            for (int e = 0; e < 4; e++) {
                int gm = g + (e >> 1) * 8;
                int col = jc * 128 + warp * 16 + nt * 8 + tig * 2 + (e & 1);
                sS[gm * FS_LD + col] = acc[nt][e] * 0.125f;
            }
        __syncthreads();
    }

    // prefetch V chunk 0 while phase B runs
    stageV(0, 0);

    // ---- Phase B: per-row dist_func + double softmax (warp owns rows w, w+8) ----
    {
        const float g0 = gammas[h];
        const float gamma = -(g0 > 20.f ? g0 : log1pf(expf(g0)));
#pragma unroll
        for (int rr = 0; rr < 2; rr++) {
            const int r  = warp + rr * 8;
            const int ig = i0 + r;
            float* row = &sS[r * FS_LD];

            // sweep 1: masked max
            float mx = -3e38f;
            for (int u = 0; u < 32; u++) {
                int j = lane + 32 * u;
                float xm = (sM[j] != 0.f) ? row[j] : -1e8f;
                mx = fmaxf(mx, xm);
            }
            mx = wmaxf(mx);

            // sweep 2: denom (all) and masked sum
            float le = 0.f, msum = 0.f;
            for (int u = 0; u < 32; u++) {
                int j = lane + 32 * u;
                float amv = sM[j];
                float xm = (amv != 0.f) ? row[j] : -1e8f;
                float e = expf(xm - mx);
                le += e;
                msum += amv * e;
            }
            le = wsumf(le);
            msum = wsumf(msum);
            const float inv = 1.f / le;
            const float total = msum * inv;

            // sweep 3: cumsum + distance decay, overwrite row with y
            float carry = 0.f, mx2 = -3e38f;
            for (int u = 0; u < 32; u++) {
                int j = lane + 32 * u;
                float x = row[j];
                float amv = sM[j];
                float e = expf(((amv != 0.f) ? x : -1e8f) - mx);
                float p = (amv != 0.f) ? e * inv : 0.f;
                float sc = p;
#pragma unroll
                for (int o = 1; o < 32; o <<= 1) {
                    float t = __shfl_up_sync(0xffffffffu, sc, o);
                    if (lane >= o) sc += t;
                }
                float cum = carry + sc;
                carry += __shfl_sync(0xffffffffu, sc, 31);
                float rem = total - cum;
                float pos = fabsf((float)(j - ig));
                float ds = sqrtf(fmaxf(rem * pos, 0.f));
                float te = expf(ds * gamma);
                te = fminf(fmaxf(te, 1e-5f), 1e5f);
                float tef = te - ((j < ig) ? sT[j] : 0.f);
                float y = (amv != 0.f) ? x * tef : -1e8f;
                mx2 = fmaxf(mx2, y);
                row[j] = y;
            }
            mx2 = wmaxf(mx2);

            // sweep 4: e2 in place + sum
            float le2 = 0.f;
            for (int u = 0; u < 32; u++) {
                int j = lane + 32 * u;
                float e2 = expf(row[j] - mx2);
                le2 += e2;
                row[j] = e2;
            }
            le2 = wsumf(le2);
            const float inv2 = 1.f / le2;

            // sweep 5: normalize -> probs
            for (int u = 0; u < 32; u++) {
                int j = lane + 32 * u;
                row[j] *= inv2;
            }
        }
    }
    __syncthreads();

    // ---- Phase C: ctx = probs(16x1024) @ V(1024x64), direct to d_out ----
    float accC[4] = {0.f, 0.f, 0.f, 0.f};
    for (int jc = 0; jc < 8; jc++) {
        if (jc < 7) { stageV(jc + 1, (jc + 1) & 1); CPWAIT(1); }
        else        { CPWAIT(0); }
        __syncthreads();
        const float* bs = &sKV[(jc & 1) * FKV_STG];
        const int nc = warp * 8 + g;
#pragma unroll
        for (int kk = 0; kk < 16; kk++) {
            int kb = kk * 8;
            int colb = jc * 128 + kb;
            unsigned aF[4];
            aF[0] = f2tf32(sS[g * FS_LD + colb + tig]);
            aF[1] = f2tf32(sS[(g + 8) * FS_LD + colb + tig]);
            aF[2] = f2tf32(sS[g * FS_LD + colb + tig + 4]);
            aF[3] = f2tf32(sS[(g + 8) * FS_LD + colb + tig + 4]);
            unsigned bF[2];
            bF[0] = f2tf32(bs[(kb + tig) * 72 + nc]);
            bF[1] = f2tf32(bs[(kb + tig + 4) * 72 + nc]);
            mma8(accC, aF, bF);
        }
        __syncthreads();
    }
#pragma unroll
    for (int e = 0; e < 4; e++) {
        int gm = g + (e >> 1) * 8;
        int gn = warp * 8 + tig * 2 + (e & 1);
        out[((size_t)b * S + i0 + gm) * OUT_W + h * 64 + gn] = accC[e];
    }
}

// ---------------- elementwise: g_convattn *= g_mq (float4) ----------------
__global__ void mul_kernel()
{
    long long i = ((long long)blockIdx.x * blockDim.x + threadIdx.x) * 4;
    if (i >= (long long)BB * S * AH) return;
    float4 a = *reinterpret_cast<const float4*>(&g_convattn[i]);
    float4 b = *reinterpret_cast<const float4*>(&g_mq[i]);
    a.x *= b.x; a.y *= b.y; a.z *= b.z; a.w *= b.w;
    *reinterpret_cast<float4*>(&g_convattn[i]) = a;
}

// ---------------- repack ck_W (384x54) -> g_ckWp (384x64, zero-padded) ----------------
__global__ void padW_kernel(const float* __restrict__ ckW)
{
    int i = blockIdx.x * blockDim.x + threadIdx.x;
    if (i >= AH * 64) return;
    int k = i >> 6, n = i & 63;
    g_ckWp[i] = (n < CKN) ? ckW[k * CKN + n] : 0.f;
}

// ---------------- tiled depthwise conv ----------------
#define DW_TS 32
#define DW_TC 256
__global__ __launch_bounds__(256) void dw_tile_kernel(
    const float* __restrict__ Kin, const float* __restrict__ dw_w)
{
    __shared__ float sK[(DW_TS + 8) * DW_TC];
    const int stile = blockIdx.x;
    const int b  = stile / (S / DW_TS);
    const int s0 = (stile % (S / DW_TS)) * DW_TS;
    const int c0 = blockIdx.y * DW_TC;
    const int tid = threadIdx.x;

    for (int i = tid * 4; i < (DW_TS + 8) * DW_TC; i += 256 * 4) {
        int r = i / DW_TC, c = i % DW_TC;
        int s = s0 + r - PAD;
        float4 v = make_float4(0.f, 0.f, 0.f, 0.f);
        if (s >= 0 && s < S)
            v = *reinterpret_cast<const float4*>(&Kin[((size_t)b * S + s) * HID + c0 + c]);
        *reinterpret_cast<float4*>(&sK[r * DW_TC + c]) = v;
    }
    __syncthreads();

    const int c = tid;
    float w[KS];
#pragma unroll
    for (int t = 0; t < KS; t++) w[t] = dw_w[(c0 + c) * KS + t];

    for (int sp = 0; sp < DW_TS; sp++) {
        float acc = 0.f;
#pragma unroll
        for (int t = 0; t < KS; t++)
            acc = fmaf(sK[(sp + t) * DW_TC + c], w[t], acc);
        g_dw[((size_t)b * S + s0 + sp) * HID + c0 + c] = acc;
    }
}

// ---------------- tiled convout ----------------
#define CO_TS 8
__global__ __launch_bounds__(384) void convout_tile_kernel(
    const float* __restrict__ ckb, float* __restrict__ out)
{
    __shared__ float sCo[(CO_TS + 8) * AH];
    __shared__ float sCk[CO_TS][H * KS];
    const int bs0 = blockIdx.x * CO_TS;
    const int b  = bs0 >> 10;
    const int s0 = bs0 & (S - 1);
    const int t = threadIdx.x;

    for (int i = t * 4; i < (CO_TS + 8) * AH; i += 384 * 4) {
        int r = i / AH, c = i % AH;
        int s = s0 + r - PAD;
        float4 v = make_float4(0.f, 0.f, 0.f, 0.f);
        if (s >= 0 && s < S)
            v = *reinterpret_cast<const float4*>(&g_co[((size_t)b * S + s) * AH + c]);
        *reinterpret_cast<float4*>(&sCo[r * AH + c]) = v;
    }
    if (t < CO_TS * H) {
        int p = t / H, h = t % H;
        float l[KS];
        float mx = -3e38f;
#pragma unroll
        for (int k = 0; k < KS; k++) {
            l[k] = g_ck[(size_t)(bs0 + p) * 64 + h * KS + k] + ckb[h * KS + k];
            mx = fmaxf(mx, l[k]);
        }
        float sum = 0.f;
#pragma unroll
        for (int k = 0; k < KS; k++) { l[k] = expf(l[k] - mx); sum += l[k]; }
        float inv = 1.f / sum;
#pragma unroll
        for (int k = 0; k < KS; k++) sCk[p][h * KS + k] = l[k] * inv;
    }
    __syncthreads();

    const int h = t >> 6;
    for (int p = 0; p < CO_TS; p++) {
        float acc = 0.f;
#pragma unroll
        for (int k = 0; k < KS; k++)
            acc = fmaf(sCk[p][h * KS + k], sCo[(p + k) * AH + t], acc);
        out[((size_t)b * S + s0 + p) * OUT_W + AH + t] = acc;
    }
}

// ---------------- td softmax (row-independent) ----------------
__global__ void tdsm_kernel(const float* __restrict__ td, const int* __restrict__ mask)
{
    __shared__ float sred[8];
    const int b = blockIdx.x;
    const int t = threadIdx.x;
    const int lane = t & 31, wid = t >> 5;
    const int j0 = t * 4;
    const float* tr = td + b * S;
    const int* mr = mask + b * S;

    float v[4]; int am[4];
#pragma unroll
    for (int u = 0; u < 4; u++) { v[u] = tr[j0 + u]; am[u] = mr[j0 + u] != 0; }

    float ss = 0.f;
#pragma unroll
    for (int u = 0; u < 4; u++) ss += v[u] * v[u];
#pragma unroll
    for (int o = 16; o; o >>= 1) ss += __shfl_xor_sync(0xffffffffu, ss, o);
    if (lane == 0) sred[wid] = ss;
    __syncthreads();
    if (wid == 0) {
        float w = (lane < 8) ? sred[lane] : 0.f;
#pragma unroll
        for (int o = 4; o; o >>= 1) w += __shfl_xor_sync(0xffffffffu, w, o);
        if (lane == 0) sred[0] = w;
    }
    __syncthreads();
    float nrm = sqrtf(sred[0]);
    float inv = 1.f / fmaxf(nrm, 1e-12f);
    __syncthreads();

    float x[4];
#pragma unroll
    for (int u = 0; u < 4; u++) x[u] = am[u] ? v[u] * inv : -1e4f;

    float mx = fmaxf(fmaxf(x[0], x[1]), fmaxf(x[2], x[3]));
#pragma unroll
    for (int o = 16; o; o >>= 1) mx = fmaxf(mx, __shfl_xor_sync(0xffffffffu, mx, o));
    if (lane == 0) sred[wid] = mx;
    __syncthreads();
    if (wid == 0) {
        float w = (lane < 8) ? sred[lane] : -1e30f;
#pragma unroll
        for (int o = 4; o; o >>= 1) w = fmaxf(w, __shfl_xor_sync(0xffffffffu, w, o));
        if (lane == 0) sred[0] = w;
    }
    __syncthreads();
    mx = sred[0];
    __syncthreads();

    float e[4], le = 0.f;
#pragma unroll
    for (int u = 0; u < 4; u++) { e[u] = expf(x[u] - mx); le += e[u]; }
#pragma unroll
    for (int o = 16; o; o >>= 1) le += __shfl_xor_sync(0xffffffffu, le, o);
    if (lane == 0) sred[wid] = le;
    __syncthreads();
    if (wid == 0) {
        float w = (lane < 8) ? sred[lane] : 0.f;
#pragma unroll
        for (int o = 4; o; o >>= 1) w += __shfl_xor_sync(0xffffffffu, w, o);
        if (lane == 0) sred[0] = w;
    }
    __syncthreads();
    float dinv = 1.f / sred[0];
#pragma unroll
    for (int u = 0; u < 4; u++) g_tdsm[b * S + j0 + u] = e[u] * dinv;
}

// ---------------- launcher ----------------
extern "C" void kernel_launch(void* const* d_in, const int* in_sizes, int n_in,
                              void* d_out, int out_size)
{
    const float* Q    = (const float*)d_in[0];
    const float* Kin  = (const float*)d_in[1];
    const float* V    = (const float*)d_in[2];
    const float* td   = (const float*)d_in[3];
    const int*   mask = (const int*)  d_in[4];
    const float* Wq   = (const float*)d_in[5];
    const float* Wk   = (const float*)d_in[6];
    const float* Wv   = (const float*)d_in[7];
    const float* dw_w = (const float*)d_in[8];
    const float* pw_w = (const float*)d_in[9];
    const float* sep_b= (const float*)d_in[10];
    const float* ck_W = (const float*)d_in[11];
    const float* ck_b = (const float*)d_in[12];
    const float* co_W = (const float*)d_in[13];
    const float* co_b = (const float*)d_in[14];
    const float* gammas=(const float*)d_in[15];
    float* out = (float*)d_out;

    float *p_mq, *p_mk, *p_mv, *p_co, *p_ca, *p_dw, *p_ck, *p_ckWp;
    cudaGetSymbolAddress((void**)&p_mq, g_mq);
    cudaGetSymbolAddress((void**)&p_mk, g_mk);
    cudaGetSymbolAddress((void**)&p_mv, g_mv);
    cudaGetSymbolAddress((void**)&p_co, g_co);
    cudaGetSymbolAddress((void**)&p_ca, g_convattn);
    cudaGetSymbolAddress((void**)&p_dw, g_dw);
    cudaGetSymbolAddress((void**)&p_ck, g_ck);
    cudaGetSymbolAddress((void**)&p_ckWp, g_ckWp);

    cudaFuncSetAttribute(tf32_proj5_w,      cudaFuncAttributeMaxDynamicSharedMemorySize, WIDE_SMEM);
    cudaFuncSetAttribute(ck_gemm_kernel,    cudaFuncAttributeMaxDynamicSharedMemorySize, PIPE_SMEM);
    cudaFuncSetAttribute(attn_fused_kernel, cudaFuncAttributeMaxDynamicSharedMemorySize, FUSED_SMEM);

    const int M = BB * S;   // 4096

    // independent prep
    tdsm_kernel<<<BB, 256>>>(td, mask);
    padW_kernel<<<(AH * 64 + 255) / 256, 256>>>(ck_W);
    dw_tile_kernel<<<dim3(BB * S / DW_TS, HID / DW_TC), 256>>>(Kin, dw_w);

    // ---- 5 projections in ONE wide launch (z = op): Q, K, V, co, pw ----
    Proj5 pr;
    pr.A[0] = Q;    pr.B[0] = Wq;   pr.bias[0] = nullptr; pr.C[0] = p_mq; pr.bt[0] = 0; pr.ldb[0] = AH;
    pr.A[1] = Kin;  pr.B[1] = Wk;   pr.bias[1] = nullptr; pr.C[1] = p_mk; pr.bt[1] = 0; pr.ldb[1] = AH;
    pr.A[2] = V;    pr.B[2] = Wv;   pr.bias[2] = nullptr; pr.C[2] = p_mv; pr.bt[2] = 0; pr.ldb[2] = AH;
    pr.A[3] = V;    pr.B[3] = co_W; pr.bias[3] = co_b;    pr.C[3] = p_co; pr.bt[3] = 0; pr.ldb[3] = AH;
    pr.A[4] = p_dw; pr.B[4] = pw_w; pr.bias[4] = sep_b;   pr.C[4] = p_ca; pr.bt[4] = 1; pr.ldb[4] = HID;
    tf32_proj5_w<<<dim3(AH / 128, M / 128, 5), 256, WIDE_SMEM>>>(pr);

    // conv_attn = mkc * mq (in place)
    mul_kernel<<<(unsigned)(((long long)BB * S * AH / 4 + 255) / 256), 256>>>();

    // ck logits on tensor cores
    ck_gemm_kernel<<<dim3(1, M / 128, 1), 256, PIPE_SMEM>>>(p_ca, p_ckWp, p_ck);

    // softmax + dynamic conv -> out[:, AH:2AH]
    convout_tile_kernel<<<M / CO_TS, 384>>>(ck_b, out);

    // fused attention: scores + dist_func + softmax + PV -> out[:, 0:AH]
    attn_fused_kernel<<<dim3(S / FR, BB * H), 256, FUSED_SMEM>>>(mask, gammas, out);
}

// round 16
// speedup vs baseline: 1.5801x; 1.5801x over previous
#include <cuda_runtime.h>
#include <cuda_bf16.h>
#include <math.h>

#define HID 768
#define NSPLITS 12
#define H 6
#define D 64
#define AH 384
#define KS 9
#define PAD 4
#define BB 4
#define S 1024
#define OUT_W 768
#define CKN 54      // H*KS

// ---------------- scratch (device globals; no allocation allowed) ----------------
__device__ float g_scores[(size_t)BB * H * S * S];     // reused for probs
__device__ float g_mq[(size_t)BB * S * AH];
__device__ float g_mk[(size_t)BB * S * AH];
__device__ float g_mv[(size_t)BB * S * AH];
__device__ float g_co[(size_t)BB * S * AH];
__device__ float g_convattn[(size_t)BB * S * AH];      // mkc, then *= mq in place
__device__ float g_dw[(size_t)BB * S * HID];
__device__ float g_tdsm[(size_t)BB * S];
__device__ float g_ck[(size_t)BB * S * 64];            // padded ck logits
__device__ float g_ckWp[(size_t)AH * 64];              // padded ck_W
__device__ float g_pv[(size_t)4 * BB * H * S * D];     // split-K=4 partials

// ---------------- common helpers ----------------
__device__ __forceinline__ unsigned f2tf32(float x) {
    unsigned y;
    asm("cvt.rna.tf32.f32 %0, %1;" : "=r"(y) : "f"(x));
    return y;
}

__device__ __forceinline__ void mma8(float* c, const unsigned* a, const unsigned* b) {
    asm volatile("mma.sync.aligned.m16n8k8.row.col.f32.tf32.tf32.f32 "
        "{%0,%1,%2,%3},{%4,%5,%6,%7},{%8,%9},{%0,%1,%2,%3};"
        : "+f"(c[0]), "+f"(c[1]), "+f"(c[2]), "+f"(c[3])
        : "r"(a[0]), "r"(a[1]), "r"(a[2]), "r"(a[3]), "r"(b[0]), "r"(b[1]));
}

__device__ __forceinline__ unsigned smem_u32(const void* p) {
    return (unsigned)__cvta_generic_to_shared(p);
}
#define CP16(dst, src) asm volatile("cp.async.ca.shared.global [%0], [%1], 16;" :: "r"(dst), "l"(src))
#define CPCOMMIT()     asm volatile("cp.async.commit_group;")
#define CPWAIT(n)      asm volatile("cp.async.wait_group %0;" :: "n"(n))

// ================= pipelined TF32 GEMM, narrow core (BM128 x BN64) =================
#define PAS_LD 36
#define PBS_LDT 36   // BT: [n][k]
#define PBS_LDN 72   // !BT: [k][n]
#define PA_STG (128 * PAS_LD)
#define PB_STG (64 * PBS_LDT)
#define PIPE_SMEM ((2 * PA_STG + 2 * PB_STG) * 4)  // 55296 B

template<bool BT>
__device__ __forceinline__ void gemm_core_pipe(
    const float* __restrict__ A, const float* __restrict__ Bm,
    float* __restrict__ C, int K, int lda, int ldb, int ldc, float alpha)
{
    extern __shared__ float dyn[];
    float* sA = dyn;
    float* sB = dyn + 2 * PA_STG;

    const int tid  = threadIdx.x;
    const int warp = tid >> 5, lane = tid & 31;
    const int g    = lane >> 2, tig = lane & 3;
    const int wm   = (warp >> 1) * 32, wn = (warp & 1) * 32;
    const int m0   = blockIdx.y * 128;
    const int n0   = blockIdx.x * 64;

    float acc[2][4][4];
#pragma unroll
    for (int mt = 0; mt < 2; mt++)
#pragma unroll
        for (int nt = 0; nt < 4; nt++)
#pragma unroll
            for (int e = 0; e < 4; e++) acc[mt][nt][e] = 0.f;

    const int nk = K >> 5;

    auto loadStage = [&](int ki, int st) {
        const int kbase = ki * 32;
#pragma unroll
        for (int it = 0; it < 4; it++) {
            int lin = tid + it * 256;
            int m = lin >> 3, kq = lin & 7;
            CP16(smem_u32(&sA[st * PA_STG + m * PAS_LD + kq * 4]),
                 A + (long long)(m0 + m) * lda + kbase + kq * 4);
        }
        if (BT) {
#pragma unroll
            for (int it = 0; it < 2; it++) {
                int lin = tid + it * 256;
                int n = lin >> 3, kq = lin & 7;
                CP16(smem_u32(&sB[st * PB_STG + n * PBS_LDT + kq * 4]),
                     Bm + (long long)(n0 + n) * ldb + kbase + kq * 4);
            }
        } else {
#pragma unroll
            for (int it = 0; it < 2; it++) {
                int lin = tid + it * 256;
                int k = lin >> 4, nq = lin & 15;
                CP16(smem_u32(&sB[st * PB_STG + k * PBS_LDN + nq * 4]),
                     Bm + (long long)(kbase + k) * ldb + n0 + nq * 4);
            }
        }
        CPCOMMIT();
    };

    loadStage(0, 0);
    for (int i = 0; i < nk; i++) {
        if (i + 1 < nk) { loadStage(i + 1, (i + 1) & 1); CPWAIT(1); }
        else            { CPWAIT(0); }
        __syncthreads();

        const float* as = &sA[(i & 1) * PA_STG];
        const float* bs = &sB[(i & 1) * PB_STG];
#pragma unroll
        for (int kk = 0; kk < 4; kk++) {
            const int kb = kk * 8;
            unsigned aF[2][4], bF[4][2];
#pragma unroll
            for (int mt = 0; mt < 2; mt++) {
                int mr = wm + mt * 16 + g;
                aF[mt][0] = f2tf32(as[mr * PAS_LD + kb + tig]);
                aF[mt][1] = f2tf32(as[(mr + 8) * PAS_LD + kb + tig]);
                aF[mt][2] = f2tf32(as[mr * PAS_LD + kb + tig + 4]);
                aF[mt][3] = f2tf32(as[(mr + 8) * PAS_LD + kb + tig + 4]);
            }
#pragma unroll
            for (int nt = 0; nt < 4; nt++) {
                int nc = wn + nt * 8 + g;
                if (BT) {
                    bF[nt][0] = f2tf32(bs[nc * PBS_LDT + kb + tig]);
                    bF[nt][1] = f2tf32(bs[nc * PBS_LDT + kb + tig + 4]);
                } else {
                    bF[nt][0] = f2tf32(bs[(kb + tig) * PBS_LDN + nc]);
                    bF[nt][1] = f2tf32(bs[(kb + tig + 4) * PBS_LDN + nc]);
                }
            }
#pragma unroll
            for (int mt = 0; mt < 2; mt++)
#pragma unroll
                for (int nt = 0; nt < 4; nt++)
                    mma8(acc[mt][nt], aF[mt], bF[nt]);
        }
        __syncthreads();
    }

#pragma unroll
    for (int mt = 0; mt < 2; mt++) {
#pragma unroll
        for (int nt = 0; nt < 4; nt++) {
            int gm0 = m0 + wm + mt * 16 + g;
            int gn0 = n0 + wn + nt * 8 + tig * 2;
            float* c = acc[mt][nt];
#pragma unroll
            for (int e = 0; e < 4; e++) {
                int gm = gm0 + (e >> 1) * 8;
                int gn = gn0 + (e & 1);
                C[(long long)gm * ldc + gn] = c[e] * alpha;
            }
        }
    }
}

// ================= wide core (BM128 x BN128), 8 warps of 32x64 =================
#define WAS_LD 36
#define WBS_LDT 36
#define WBS_LDN 136
#define WA_STG (128 * WAS_LD)
#define WB_STG (128 * WBS_LDT)
#define WIDE_SMEM ((2 * WA_STG + 2 * WB_STG) * 4)  // 73728 B

template<bool BT>
__device__ __forceinline__ void gemm_core_wide(
    const float* __restrict__ A, const float* __restrict__ Bm,
    const float* __restrict__ bias, float* __restrict__ C,
    int K, int lda, int ldb, int ldc, float alpha)
{
    extern __shared__ float dyn[];
    float* sA = dyn;
    float* sB = dyn + 2 * WA_STG;

    const int tid  = threadIdx.x;
    const int warp = tid >> 5, lane = tid & 31;
    const int g    = lane >> 2, tig = lane & 3;
    const int wm   = (warp >> 1) * 32, wn = (warp & 1) * 64;
    const int m0   = blockIdx.y * 128;
    const int n0   = blockIdx.x * 128;

    float acc[2][8][4];
#pragma unroll
    for (int mt = 0; mt < 2; mt++)
#pragma unroll
        for (int nt = 0; nt < 8; nt++)
#pragma unroll
            for (int e = 0; e < 4; e++) acc[mt][nt][e] = 0.f;

    const int nk = K >> 5;

    auto loadStage = [&](int ki, int st) {
        const int kbase = ki * 32;
#pragma unroll
        for (int it = 0; it < 4; it++) {
            int lin = tid + it * 256;
            int m = lin >> 3, kq = lin & 7;
            CP16(smem_u32(&sA[st * WA_STG + m * WAS_LD + kq * 4]),
                 A + (long long)(m0 + m) * lda + kbase + kq * 4);
        }
        if (BT) {
#pragma unroll
            for (int it = 0; it < 4; it++) {
                int lin = tid + it * 256;
                int n = lin >> 3, kq = lin & 7;
                CP16(smem_u32(&sB[st * WB_STG + n * WBS_LDT + kq * 4]),
                     Bm + (long long)(n0 + n) * ldb + kbase + kq * 4);
            }
        } else {
#pragma unroll
            for (int it = 0; it < 4; it++) {
                int lin = tid + it * 256;
                int k = lin >> 5, nq = lin & 31;
                CP16(smem_u32(&sB[st * WB_STG + k * WBS_LDN + nq * 4]),
                     Bm + (long long)(kbase + k) * ldb + n0 + nq * 4);
            }
        }
        CPCOMMIT();
    };

    loadStage(0, 0);
    for (int i = 0; i < nk; i++) {
        if (i + 1 < nk) { loadStage(i + 1, (i + 1) & 1); CPWAIT(1); }
        else            { CPWAIT(0); }
        __syncthreads();

        const float* as = &sA[(i & 1) * WA_STG];
        const float* bs = &sB[(i & 1) * WB_STG];
#pragma unroll
        for (int kk = 0; kk < 4; kk++) {
            const int kb = kk * 8;
            unsigned aF[2][4], bF[8][2];
#pragma unroll
            for (int mt = 0; mt < 2; mt++) {
                int mr = wm + mt * 16 + g;
                aF[mt][0] = f2tf32(as[mr * WAS_LD + kb + tig]);
                aF[mt][1] = f2tf32(as[(mr + 8) * WAS_LD + kb + tig]);
                aF[mt][2] = f2tf32(as[mr * WAS_LD + kb + tig + 4]);
                aF[mt][3] = f2tf32(as[(mr + 8) * WAS_LD + kb + tig + 4]);
            }
#pragma unroll
            for (int nt = 0; nt < 8; nt++) {
                int nc = wn + nt * 8 + g;
                if (BT) {
                    bF[nt][0] = f2tf32(bs[nc * WBS_LDT + kb + tig]);
                    bF[nt][1] = f2tf32(bs[nc * WBS_LDT + kb + tig + 4]);
                } else {
                    bF[nt][0] = f2tf32(bs[(kb + tig) * WBS_LDN + nc]);
                    bF[nt][1] = f2tf32(bs[(kb + tig + 4) * WBS_LDN + nc]);
                }
            }
#pragma unroll
            for (int mt = 0; mt < 2; mt++)
#pragma unroll
                for (int nt = 0; nt < 8; nt++)
                    mma8(acc[mt][nt], aF[mt], bF[nt]);
        }
        __syncthreads();
    }

#pragma unroll
    for (int mt = 0; mt < 2; mt++) {
#pragma unroll
        for (int nt = 0; nt < 8; nt++) {
            int gm0 = m0 + wm + mt * 16 + g;
            int gn0 = n0 + wn + nt * 8 + tig * 2;
            float* c = acc[mt][nt];
#pragma unroll
            for (int e = 0; e < 4; e++) {
                int gm = gm0 + (e >> 1) * 8;
                int gn = gn0 + (e & 1);
                float v = c[e] * alpha;
                if (bias) v += bias[gn];
                C[(long long)gm * ldc + gn] = v;
            }
        }
    }
}

// ---- 5 projections (Q,K,V,co,pw) in a single wide launch ----
struct Proj5 {
    const float* A[5];
    const float* B[5];
    const float* bias[5];
    float* C[5];
    int bt[5];
    int ldb[5];
};

__global__ __launch_bounds__(256) void tf32_proj5_w(Proj5 p)
{
    int op = blockIdx.z;
    if (p.bt[op])
        gemm_core_wide<true>(p.A[op], p.B[op], p.bias[op], p.C[op],
                             HID, HID, p.ldb[op], AH, 1.f);
    else
        gemm_core_wide<false>(p.A[op], p.B[op], p.bias[op], p.C[op],
                              HID, HID, p.ldb[op], AH, 1.f);
}

// ---- scores GEMM (wide, BT): per (b,h) batch ----
__global__ __launch_bounds__(256) void scores_kernel_w(
    const float* __restrict__ mq, const float* __restrict__ mk, float* __restrict__ scores)
{
    int z = blockIdx.z;
    int b = z / H, h = z % H;
    gemm_core_wide<true>(mq + (size_t)b * S * AH + h * D,
                         mk + (size_t)b * S * AH + h * D,
                         nullptr,
                         scores + (size_t)z * S * S,
                         D, AH, AH, S, 0.125f);
}

// ---- ck GEMM (narrow core) ----
__global__ __launch_bounds__(256) void ck_gemm_kernel(
    const float* __restrict__ ca, const float* __restrict__ ckWp, float* __restrict__ ck)
{
    gemm_core_pipe<false>(ca, ckWp, ck, AH, AH, 64, 64, 1.f);
}

// ---- PV split-K=4 (narrow core, N=64), z = bh*4 + kh ----
__global__ __launch_bounds__(256) void pv_split_kernel(
    const float* __restrict__ scores, const float* __restrict__ mv, float* __restrict__ pv)
{
    int z = blockIdx.z;
    int bh = z >> 2, kh = z & 3;
    int b = bh / H, h = bh % H;
    gemm_core_pipe<false>(scores + (size_t)bh * S * S + kh * 256,
                          mv + (size_t)b * S * AH + (size_t)(kh * 256) * AH + h * D,
                          pv + (size_t)(kh * (BB * H) + bh) * S * D,
                          256, S, AH, D, 1.f);
}

// ---- sum the four PV partials into d_out (interleaved ctx layout) ----
__global__ void pv_add_kernel(float* __restrict__ out)
{
    long long i4 = ((long long)blockIdx.x * blockDim.x + threadIdx.x) * 4;
    if (i4 >= (long long)BB * H * S * D) return;
    int d  = (int)(i4 & (D - 1));
    int s  = (int)((i4 >> 6) & (S - 1));
    int bh = (int)(i4 >> 16);
    int b = bh / H, h = bh % H;
    size_t p0 = (size_t)bh * S * D + (size_t)s * D + d;
    const size_t stride = (size_t)(BB * H) * S * D;
    float4 a = *reinterpret_cast<const float4*>(&g_pv[p0]);
#pragma unroll
    for (int kh = 1; kh < 4; kh++) {
        float4 c = *reinterpret_cast<const float4*>(&g_pv[p0 + kh * stride]);
        a.x += c.x; a.y += c.y; a.z += c.z; a.w += c.w;
    }
    *reinterpret_cast<float4*>(&out[((size_t)b * S + s) * OUT_W + h * D + d]) = a;
}

// ---------------- elementwise: g_convattn *= g_mq (float4) ----------------
__global__ void mul_kernel()
{
    long long i = ((long long)blockIdx.x * blockDim.x + threadIdx.x) * 4;
    if (i >= (long long)BB * S * AH) return;
    float4 a = *reinterpret_cast<const float4*>(&g_convattn[i]);
    float4 b = *reinterpret_cast<const float4*>(&g_mq[i]);
    a.x *= b.x; a.y *= b.y; a.z *= b.z; a.w *= b.w;
    *reinterpret_cast<float4*>(&g_convattn[i]) = a;
}

// ---------------- repack ck_W (384x54) -> g_ckWp (384x64, zero-padded) ----------------
__global__ void padW_kernel(const float* __restrict__ ckW)
{
    int i = blockIdx.x * blockDim.x + threadIdx.x;
    if (i >= AH * 64) return;
    int k = i >> 6, n = i & 63;
    g_ckWp[i] = (n < CKN) ? ckW[k * CKN + n] : 0.f;
}

// ---------------- tiled depthwise conv ----------------
#define DW_TS 32
#define DW_TC 256
__global__ __launch_bounds__(256) void dw_tile_kernel(
    const float* __restrict__ Kin, const float* __restrict__ dw_w)
{
    __shared__ float sK[(DW_TS + 8) * DW_TC];
    const int stile = blockIdx.x;
    const int b  = stile / (S / DW_TS);
    const int s0 = (stile % (S / DW_TS)) * DW_TS;
    const int c0 = blockIdx.y * DW_TC;
    const int tid = threadIdx.x;

    for (int i = tid * 4; i < (DW_TS + 8) * DW_TC; i += 256 * 4) {
        int r = i / DW_TC, c = i % DW_TC;
        int s = s0 + r - PAD;
        float4 v = make_float4(0.f, 0.f, 0.f, 0.f);
        if (s >= 0 && s < S)
            v = *reinterpret_cast<const float4*>(&Kin[((size_t)b * S + s) * HID + c0 + c]);
        *reinterpret_cast<float4*>(&sK[r * DW_TC + c]) = v;
    }
    __syncthreads();

    const int c = tid;
    float w[KS];
#pragma unroll
    for (int t = 0; t < KS; t++) w[t] = dw_w[(c0 + c) * KS + t];

    for (int sp = 0; sp < DW_TS; sp++) {
        float acc = 0.f;
#pragma unroll
        for (int t = 0; t < KS; t++)
            acc = fmaf(sK[(sp + t) * DW_TC + c], w[t], acc);
        g_dw[((size_t)b * S + s0 + sp) * HID + c0 + c] = acc;
    }
}

// ---------------- tiled convout ----------------
#define CO_TS 8
__global__ __launch_bounds__(384) void convout_tile_kernel(
    const float* __restrict__ ckb, float* __restrict__ out)
{
    __shared__ float sCo[(CO_TS + 8) * AH];
    __shared__ float sCk[CO_TS][H * KS];
    const int bs0 = blockIdx.x * CO_TS;
    const int b  = bs0 >> 10;
    const int s0 = bs0 & (S - 1);
    const int t = threadIdx.x;

    for (int i = t * 4; i < (CO_TS + 8) * AH; i += 384 * 4) {
        int r = i / AH, c = i % AH;
        int s = s0 + r - PAD;
        float4 v = make_float4(0.f, 0.f, 0.f, 0.f);
        if (s >= 0 && s < S)
            v = *reinterpret_cast<const float4*>(&g_co[((size_t)b * S + s) * AH + c]);
        *reinterpret_cast<float4*>(&sCo[r * AH + c]) = v;
    }
    if (t < CO_TS * H) {
        int p = t / H, h = t % H;
        float l[KS];
        float mx = -3e38f;
#pragma unroll
        for (int k = 0; k < KS; k++) {
            l[k] = g_ck[(size_t)(bs0 + p) * 64 + h * KS + k] + ckb[h * KS + k];
            mx = fmaxf(mx, l[k]);
        }
        float sum = 0.f;
#pragma unroll
        for (int k = 0; k < KS; k++) { l[k] = expf(l[k] - mx); sum += l[k]; }
        float inv = 1.f / sum;
#pragma unroll
        for (int k = 0; k < KS; k++) sCk[p][h * KS + k] = l[k] * inv;
    }
    __syncthreads();

    const int h = t >> 6;
    for (int p = 0; p < CO_TS; p++) {
        float acc = 0.f;
#pragma unroll
        for (int k = 0; k < KS; k++)
            acc = fmaf(sCk[p][h * KS + k], sCo[(p + k) * AH + t], acc);
        out[((size_t)b * S + s0 + p) * OUT_W + AH + t] = acc;
    }
}

// ---------------- td softmax (row-independent) ----------------
__global__ void tdsm_kernel(const float* __restrict__ td, const int* __restrict__ mask)
{
    __shared__ float sred[8];
    const int b = blockIdx.x;
    const int t = threadIdx.x;
    const int lane = t & 31, wid = t >> 5;
    const int j0 = t * 4;
    const float* tr = td + b * S;
    const int* mr = mask + b * S;

    float v[4]; int am[4];
#pragma unroll
    for (int u = 0; u < 4; u++) { v[u] = tr[j0 + u]; am[u] = mr[j0 + u] != 0; }

    float ss = 0.f;
#pragma unroll
    for (int u = 0; u < 4; u++) ss += v[u] * v[u];
#pragma unroll
    for (int o = 16; o; o >>= 1) ss += __shfl_xor_sync(0xffffffffu, ss, o);
    if (lane == 0) sred[wid] = ss;
    __syncthreads();
    if (wid == 0) {
        float w = (lane < 8) ? sred[lane] : 0.f;
#pragma unroll
        for (int o = 4; o; o >>= 1) w += __shfl_xor_sync(0xffffffffu, w, o);
        if (lane == 0) sred[0] = w;
    }
    __syncthreads();
    float nrm = sqrtf(sred[0]);
    float inv = 1.f / fmaxf(nrm, 1e-12f);
    __syncthreads();

    float x[4];
#pragma unroll
    for (int u = 0; u < 4; u++) x[u] = am[u] ? v[u] * inv : -1e4f;

    float mx = fmaxf(fmaxf(x[0], x[1]), fmaxf(x[2], x[3]));
#pragma unroll
    for (int o = 16; o; o >>= 1) mx = fmaxf(mx, __shfl_xor_sync(0xffffffffu, mx, o));
    if (lane == 0) sred[wid] = mx;
    __syncthreads();
    if (wid == 0) {
        float w = (lane < 8) ? sred[lane] : -1e30f;
#pragma unroll
        for (int o = 4; o; o >>= 1) w = fmaxf(w, __shfl_xor_sync(0xffffffffu, w, o));
        if (lane == 0) sred[0] = w;
    }
    __syncthreads();
    mx = sred[0];
    __syncthreads();

    float e[4], le = 0.f;
#pragma unroll
    for (int u = 0; u < 4; u++) { e[u] = expf(x[u] - mx); le += e[u]; }
#pragma unroll
    for (int o = 16; o; o >>= 1) le += __shfl_xor_sync(0xffffffffu, le, o);
    if (lane == 0) sred[wid] = le;
    __syncthreads();
    if (wid == 0) {
        float w = (lane < 8) ? sred[lane] : 0.f;
#pragma unroll
        for (int o = 4; o; o >>= 1) w += __shfl_xor_sync(0xffffffffu, w, o);
        if (lane == 0) sred[0] = w;
    }
    __syncthreads();
    float dinv = 1.f / sred[0];
#pragma unroll
    for (int u = 0; u < 4; u++) g_tdsm[b * S + j0 + u] = e[u] * dinv;
}

// ---------------- fused per-row score pipeline ----------------
__device__ __forceinline__ float blockMax256(float v, float* sm, int lane, int wid)
{
#pragma unroll
    for (int o = 16; o; o >>= 1) v = fmaxf(v, __shfl_xor_sync(0xffffffffu, v, o));
    if (lane == 0) sm[wid] = v;
    __syncthreads();
    if (wid == 0) {
        float w = (lane < 8) ? sm[lane] : -3e38f;
#pragma unroll
        for (int o = 4; o; o >>= 1) w = fmaxf(w, __shfl_xor_sync(0xffffffffu, w, o));
        if (lane == 0) sm[0] = w;
    }
    __syncthreads();
    float r = sm[0];
    __syncthreads();
    return r;
}

__device__ __forceinline__ float blockSum256(float v, float* sm, int lane, int wid)
{
#pragma unroll
    for (int o = 16; o; o >>= 1) v += __shfl_xor_sync(0xffffffffu, v, o);
    if (lane == 0) sm[wid] = v;
    __syncthreads();
    if (wid == 0) {
        float w = (lane < 8) ? sm[lane] : 0.f;
#pragma unroll
        for (int o = 4; o; o >>= 1) w += __shfl_xor_sync(0xffffffffu, w, o);
        if (lane == 0) sm[0] = w;
    }
    __syncthreads();
    float r = sm[0];
    __syncthreads();
    return r;
}

__global__ void row_pipeline_kernel(const int* __restrict__ mask,
                                    const float* __restrict__ gammas)
{
    __shared__ float sred[8];
    __shared__ float swarp[8];
    const int t = threadIdx.x;
    const int lane = t & 31, wid = t >> 5;
    const int row = blockIdx.x;              // (b*H + h)*S + i
    const int i  = row & (S - 1);
    const int bh = row >> 10;
    const int h  = bh % H;
    const int b  = bh / H;
    float* srow = g_scores + (size_t)row * S;
    const int j0 = t * 4;

    float4 x4 = *reinterpret_cast<const float4*>(srow + j0);
    float x[4] = { x4.x, x4.y, x4.z, x4.w };
    const int* mr = mask + b * S;
    int am[4];
#pragma unroll
    for (int u = 0; u < 4; u++) am[u] = mr[j0 + u] != 0;
    float xm[4];
#pragma unroll
    for (int u = 0; u < 4; u++) xm[u] = am[u] ? x[u] : -1e8f;

    float mx = fmaxf(fmaxf(xm[0], xm[1]), fmaxf(xm[2], xm[3]));
    mx = blockMax256(mx, sred, lane, wid);
    float e[4], le = 0.f;
#pragma unroll
    for (int u = 0; u < 4; u++) { e[u] = expf(xm[u] - mx); le += e[u]; }
    float denom = blockSum256(le, sred, lane, wid);
    float inv = 1.f / denom;
    float p[4];
#pragma unroll
    for (int u = 0; u < 4; u++) p[u] = am[u] ? e[u] * inv : 0.f;

    float lp[4]; float run = 0.f;
#pragma unroll
    for (int u = 0; u < 4; u++) { run += p[u]; lp[u] = run; }
    float tot = run;
    float sc = tot;
#pragma unroll
    for (int o = 1; o < 32; o <<= 1) {
        float v = __shfl_up_sync(0xffffffffu, sc, o);
        if (lane >= o) sc += v;
    }
    if (lane == 31) swarp[wid] = sc;
    __syncthreads();
    if (wid == 0) {
        float v = (lane < 8) ? swarp[lane] : 0.f;
#pragma unroll
        for (int o = 1; o < 8; o <<= 1) {
            float w = __shfl_up_sync(0xffffffffu, v, o);
            if (lane >= o) v += w;
        }
        if (lane < 8) swarp[lane] = v;
    }
    __syncthreads();
    float off = ((wid > 0) ? swarp[wid - 1] : 0.f) + (sc - tot);
    float total = swarp[7];
    __syncthreads();

    const float g0 = gammas[h];
    const float gamma = -(g0 > 20.f ? g0 : log1pf(expf(g0)));
    const float* tdr = g_tdsm + b * S;

    float y[4];
#pragma unroll
    for (int u = 0; u < 4; u++) {
        int j = j0 + u;
        float cum = off + lp[u];
        float rem = total - cum;
        float pos = fabsf((float)(j - i));
        float ds = sqrtf(fmaxf(rem * pos, 0.f));
        float te = expf(ds * gamma);
        te = fminf(fmaxf(te, 1e-5f), 1e5f);
        float tef = te - ((j < i) ? tdr[j] : 0.f);
        y[u] = am[u] ? x[u] * tef : -1e8f;
    }

    float mx2 = fmaxf(fmaxf(y[0], y[1]), fmaxf(y[2], y[3]));
    mx2 = blockMax256(mx2, sred, lane, wid);
    float e2[4], le2 = 0.f;
#pragma unroll
    for (int u = 0; u < 4; u++) { e2[u] = expf(y[u] - mx2); le2 += e2[u]; }
    float denom2 = blockSum256(le2, sred, lane, wid);
    float inv2 = 1.f / denom2;
    float4 o4;
    o4.x = e2[0] * inv2; o4.y = e2[1] * inv2; o4.z = e2[2] * inv2; o4.w = e2[3] * inv2;
    *reinterpret_cast<float4*>(srow + j0) = o4;
}

// ---------------- launcher ----------------
extern "C" void kernel_launch(void* const* d_in, const int* in_sizes, int n_in,
                              void* d_out, int out_size)
{
    const float* Q    = (const float*)d_in[0];
    const float* Kin  = (const float*)d_in[1];
    const float* V    = (const float*)d_in[2];
    const float* td   = (const float*)d_in[3];
    const int*   mask = (const int*)  d_in[4];
    const float* Wq   = (const float*)d_in[5];
    const float* Wk   = (const float*)d_in[6];
    const float* Wv   = (const float*)d_in[7];
    const float* dw_w = (const float*)d_in[8];
    const float* pw_w = (const float*)d_in[9];
    const float* sep_b= (const float*)d_in[10];
    const float* ck_W = (const float*)d_in[11];
    const float* ck_b = (const float*)d_in[12];
    const float* co_W = (const float*)d_in[13];
    const float* co_b = (const float*)d_in[14];
    const float* gammas=(const float*)d_in[15];
    float* out = (float*)d_out;

    float *p_scores, *p_mq, *p_mk, *p_mv, *p_co, *p_ca, *p_dw, *p_ck, *p_ckWp, *p_pv;
    cudaGetSymbolAddress((void**)&p_scores, g_scores);
    cudaGetSymbolAddress((void**)&p_mq, g_mq);
    cudaGetSymbolAddress((void**)&p_mk, g_mk);
    cudaGetSymbolAddress((void**)&p_mv, g_mv);
    cudaGetSymbolAddress((void**)&p_co, g_co);
    cudaGetSymbolAddress((void**)&p_ca, g_convattn);
    cudaGetSymbolAddress((void**)&p_dw, g_dw);
    cudaGetSymbolAddress((void**)&p_ck, g_ck);
    cudaGetSymbolAddress((void**)&p_ckWp, g_ckWp);
    cudaGetSymbolAddress((void**)&p_pv, g_pv);

    cudaFuncSetAttribute(tf32_proj5_w,    cudaFuncAttributeMaxDynamicSharedMemorySize, WIDE_SMEM);
    cudaFuncSetAttribute(scores_kernel_w, cudaFuncAttributeMaxDynamicSharedMemorySize, WIDE_SMEM);
    cudaFuncSetAttribute(ck_gemm_kernel,  cudaFuncAttributeMaxDynamicSharedMemorySize, PIPE_SMEM);
    cudaFuncSetAttribute(pv_split_kernel, cudaFuncAttributeMaxDynamicSharedMemorySize, PIPE_SMEM);

    const int M = BB * S;   // 4096

    // secondary stream + fork/join events (graph-capturable pattern; created per
    // call, never destroyed mid-capture; host-side objects only)
    cudaStream_t s2;
    cudaStreamCreateWithFlags(&s2, cudaStreamNonBlocking);
    cudaEvent_t e0, eT, eP, eJ;
    cudaEventCreateWithFlags(&e0, cudaEventDisableTiming);
    cudaEventCreateWithFlags(&eT, cudaEventDisableTiming);
    cudaEventCreateWithFlags(&eP, cudaEventDisableTiming);
    cudaEventCreateWithFlags(&eJ, cudaEventDisableTiming);

    // fork: s2 branches off the main (legacy) stream
    cudaEventRecord(e0, 0);
    cudaStreamWaitEvent(s2, e0, 0);

    // s2: independent prep (overlaps dw + proj5 on main stream)
    tdsm_kernel<<<BB, 256, 0, s2>>>(td, mask);
    padW_kernel<<<(AH * 64 + 255) / 256, 256, 0, s2>>>(ck_W);
    cudaEventRecord(eT, s2);

    // main: depthwise conv, then the 5-projection launch
    dw_tile_kernel<<<dim3(BB * S / DW_TS, HID / DW_TC), 256>>>(Kin, dw_w);

    Proj5 pr;
    pr.A[0] = Q;    pr.B[0] = Wq;   pr.bias[0] = nullptr; pr.C[0] = p_mq; pr.bt[0] = 0; pr.ldb[0] = AH;
    pr.A[1] = Kin;  pr.B[1] = Wk;   pr.bias[1] = nullptr; pr.C[1] = p_mk; pr.bt[1] = 0; pr.ldb[1] = AH;
    pr.A[2] = V;    pr.B[2] = Wv;   pr.bias[2] = nullptr; pr.C[2] = p_mv; pr.bt[2] = 0; pr.ldb[2] = AH;
    pr.A[3] = V;    pr.B[3] = co_W; pr.bias[3] = co_b;    pr.C[3] = p_co; pr.bt[3] = 0; pr.ldb[3] = AH;
    pr.A[4] = p_dw; pr.B[4] = pw_w; pr.bias[4] = sep_b;   pr.C[4] = p_ca; pr.bt[4] = 1; pr.ldb[4] = HID;
    tf32_proj5_w<<<dim3(AH / 128, M / 128, 5), 256, WIDE_SMEM>>>(pr);
    cudaEventRecord(eP, 0);

    // s2: conv branch (mul -> ck GEMM -> convout), overlaps attention GEMMs
    cudaStreamWaitEvent(s2, eP, 0);
    mul_kernel<<<(unsigned)(((long long)BB * S * AH / 4 + 255) / 256), 256, 0, s2>>>();
    ck_gemm_kernel<<<dim3(1, M / 128, 1), 256, PIPE_SMEM, s2>>>(p_ca, p_ckWp, p_ck);
    convout_tile_kernel<<<M / CO_TS, 384, 0, s2>>>(ck_b, out);
    cudaEventRecord(eJ, s2);

    // main: attention chain
    scores_kernel_w<<<dim3(S / 128, S / 128, BB * H), 256, WIDE_SMEM>>>(p_mq, p_mk, p_scores);
    cudaStreamWaitEvent(0, eT, 0);   // row pipeline needs g_tdsm from s2
    row_pipeline_kernel<<<BB * H * S, 256>>>(mask, gammas);
    pv_split_kernel<<<dim3(1, S / 128, BB * H * 4), 256, PIPE_SMEM>>>(p_scores, p_mv, p_pv);
    pv_add_kernel<<<(unsigned)(((long long)BB * H * S * D / 4 + 255) / 256), 256>>>(out);

    // join: main stream waits for the conv branch before capture ends
    cudaStreamWaitEvent(0, eJ, 0);
}